// round 16
// baseline (speedup 1.0000x reference)
#include <cuda_runtime.h>

#define D      64
#define NSEG   8192
#define OUT    128
#define NBLK   740   // 148 SMs x 5 resident blocks (51-reg cap, 205KB smem/SM)

__device__ int g_counter[2];   // dynamic segment queues, one per type

__device__ __forceinline__ void fmax4(float4& a, const float4 b) {
    a.x = fmaxf(a.x, b.x); a.y = fmaxf(a.y, b.y);
    a.z = fmaxf(a.z, b.z); a.w = fmaxf(a.w, b.w);
}

// ---------------------------------------------------------------------------
// Init: zero output (== relu floor) and both work-queue counters.
// Stream-ordered before the main kernel -> deterministic per replay.
// ---------------------------------------------------------------------------
__global__ void init_kernel(float* __restrict__ out)
{
    out[threadIdx.x] = 0.0f;
    if (threadIdx.x < 2) g_counter[threadIdx.x] = 0;
}

// ---------------------------------------------------------------------------
// Persistent fused kernel — R11 WIN structure verbatim (164 us, DRAM 78.7%),
// with ONE change: occupancy 4 -> 5 blocks/SM (launch_bounds(256,5), 740
// blocks). R12 (sync removal) and R15 (big-first scheduling) were both null,
// leaving occupancy (measured 48%) as the last untested first-order lever:
// during each block's reduce+epilogue+pop no LDGs issue, and only the other
// resident blocks cover the stream.
//
// Per segment: R3 streaming max loop -> 2-level shared reduce -> split-K
// epilogue from conflict-free padded smem W (sw[256][9] float4). lmax
// accumulates in registers; one atomicMax per channel pair at block exit.
// relu(max)==max(relu); int-bit atomicMax exact for non-negative floats.
// ptr arrays are int32 (JAX x64 disabled downcasts the int64 ptr).
// ---------------------------------------------------------------------------
__global__ void __launch_bounds__(256, 5)
seg_max_linear_kernel(const float* __restrict__ x_a,
                      const float* __restrict__ x_b,
                      const float* __restrict__ W_a,
                      const float* __restrict__ W_b,
                      const float* __restrict__ b_a,
                      const float* __restrict__ b_b,
                      const int* __restrict__ ptr_a,
                      const int* __restrict__ ptr_b,
                      float* __restrict__ out)
{
    const int ctype = blockIdx.x & 1;

    const float* x    = ctype ? x_b   : x_a;
    const int*   ptr  = ctype ? ptr_b : ptr_a;
    const float* W    = ctype ? W_b   : W_a;
    const float* bias = ctype ? b_b   : b_a;

    const int tid = threadIdx.x;               // 256
    const int c4  = tid & 15;                  // float4 column 0..15
    const int rg  = tid >> 4;                  // row group 0..15
    const int o   = tid >> 1;                  // epilogue output channel
    const int h   = tid & 1;                   // epilogue K-half

    __shared__ float4 sw[256][9];              // padded W, conflict-free
    __shared__ float4 sm[16][16];              // reduce scratch
    __shared__ float4 segv[D / 4];             // this segment's max vector
    __shared__ int    swork;

    // W -> shared once: coalesced LDG, scattered conflict-free STS.
    {
        const float4* __restrict__ W4g = reinterpret_cast<const float4*>(W);
        #pragma unroll
        for (int i = 0; i < 8; i++) {
            int f = tid + i * 256;             // float4 linear index into W
            float4 v = W4g[f];
            int row = f >> 4;                  // output row 0..127
            int kk  = f & 15;                  // float4 within row
            sw[(row << 1) | (kk >> 3)][kk & 7] = v;
        }
    }
    const float bo = bias[o];

    const float4* __restrict__ xv = reinterpret_cast<const float4*>(x);
    const float NEG = -3.402823466e38f;

    float lmax = 0.0f;                         // relu floor, running block max

    while (true) {
        if (tid == 0) swork = atomicAdd(&g_counter[ctype], 1);
        __syncthreads();                       // also covers sw visibility
        const int g = swork;
        if (g >= NSEG) break;

        const int gs = ptr[g];
        const int ge = ptr[g + 1];

        float4 m0 = make_float4(NEG, NEG, NEG, NEG);
        float4 m1 = m0, m2 = m0, m3 = m0;

        long long row = (long long)gs + rg;
        for (; row + 48 < ge; row += 64) {
            const float4* p = xv + row * (D / 4) + c4;
            float4 v0 = __ldcs(p);
            float4 v1 = __ldcs(p + 16 * (D / 4));
            float4 v2 = __ldcs(p + 32 * (D / 4));
            float4 v3 = __ldcs(p + 48 * (D / 4));
            fmax4(m0, v0); fmax4(m1, v1); fmax4(m2, v2); fmax4(m3, v3);
        }
        for (; row < ge; row += 16) {
            float4 v0 = __ldcs(xv + row * (D / 4) + c4);
            fmax4(m0, v0);
        }
        fmax4(m0, m1); fmax4(m2, m3); fmax4(m0, m2);

        sm[rg][c4] = m0;
        __syncthreads();

        if (tid < 16) {
            float4 m = sm[0][tid];
            #pragma unroll
            for (int j = 1; j < 16; j++)
                fmax4(m, sm[j][tid]);
            segv[tid] = m;
        }
        __syncthreads();

        // Epilogue: split-K half-dot from smem W (no register W copy).
        float a0 = 0.f, a1 = 0.f, a2 = 0.f, a3 = 0.f;
        #pragma unroll
        for (int k = 0; k < 8; k++) {
            float4 ww = sw[tid][k];            // W[o, h*32+4k .. +4)
            float4 u  = segv[h * 8 + k];
            a0 = fmaf(ww.x, u.x, a0);
            a1 = fmaf(ww.y, u.y, a1);
            a2 = fmaf(ww.z, u.z, a2);
            a3 = fmaf(ww.w, u.w, a3);
        }
        float hd    = (a0 + a1) + (a2 + a3);
        float other = __shfl_xor_sync(0xffffffffu, hd, 1);
        lmax = fmaxf(lmax, hd + other + bo);
        // next iteration's top-of-loop __syncthreads orders segv reuse
    }

    if (h == 0)
        atomicMax(reinterpret_cast<int*>(out) + o, __float_as_int(lmax));
}

// ---------------------------------------------------------------------------
extern "C" void kernel_launch(void* const* d_in, const int* in_sizes, int n_in,
                              void* d_out, int out_size)
{
    const float* x_a   = (const float*)d_in[0];
    const float* x_b   = (const float*)d_in[1];
    const float* W_a   = (const float*)d_in[2];
    const float* W_b   = (const float*)d_in[3];
    const float* b_a   = (const float*)d_in[4];
    const float* b_b   = (const float*)d_in[5];
    const int*   ptr_a = (const int*)d_in[6];
    const int*   ptr_b = (const int*)d_in[7];
    float* out = (float*)d_out;

    init_kernel<<<1, OUT>>>(out);
    seg_max_linear_kernel<<<NBLK, 256>>>(x_a, x_b, W_a, W_b,
                                         b_a, b_b, ptr_a, ptr_b, out);
}

// round 17
// speedup vs baseline: 1.3889x; 1.3889x over previous
#include <cuda_runtime.h>

#define D      64
#define NSEG   8192
#define OUT    128
#define NBLK   592   // 148 SMs x 4 resident blocks (64-reg cap) — R16 proved 5 is worse

__device__ int g_counter[2];   // dynamic segment queues, one per type

__device__ __forceinline__ void fmax4(float4& a, const float4 b) {
    a.x = fmaxf(a.x, b.x); a.y = fmaxf(a.y, b.y);
    a.z = fmaxf(a.z, b.z); a.w = fmaxf(a.w, b.w);
}

// ---------------------------------------------------------------------------
// Init: zero output (== relu floor) and both work-queue counters.
// Stream-ordered before the main kernel -> deterministic per replay.
// ---------------------------------------------------------------------------
__global__ void init_kernel(float* __restrict__ out)
{
    out[threadIdx.x] = 0.0f;
    if (threadIdx.x < 2) g_counter[threadIdx.x] = 0;
}

// ---------------------------------------------------------------------------
// Persistent fused kernel — R11 WIN structure (164 us, DRAM 78.7%) with ONE
// change: the serial MLP=1 tail loop is replaced by a single predicated step
// issuing all (<=3) remaining row loads independently. ~13% of streamed data
// previously ran at MLP=1 with a dependent ~577-cyc DRAM latency per step;
// now those loads overlap. R12/R15/R16 established that sync overhead,
// scheduling order, and higher occupancy are NOT the binder — register-MLP is.
//
// Per segment: streaming max -> 2-level shared reduce -> split-K epilogue
// from conflict-free padded smem W (sw[256][9] float4). lmax accumulates in
// registers; one atomicMax per channel pair at block exit.
// relu(max)==max(relu); int-bit atomicMax exact for non-negative floats.
// ptr arrays are int32 (JAX x64 disabled downcasts the int64 ptr).
// ---------------------------------------------------------------------------
__global__ void __launch_bounds__(256, 4)
seg_max_linear_kernel(const float* __restrict__ x_a,
                      const float* __restrict__ x_b,
                      const float* __restrict__ W_a,
                      const float* __restrict__ W_b,
                      const float* __restrict__ b_a,
                      const float* __restrict__ b_b,
                      const int* __restrict__ ptr_a,
                      const int* __restrict__ ptr_b,
                      float* __restrict__ out)
{
    const int ctype = blockIdx.x & 1;

    const float* x    = ctype ? x_b   : x_a;
    const int*   ptr  = ctype ? ptr_b : ptr_a;
    const float* W    = ctype ? W_b   : W_a;
    const float* bias = ctype ? b_b   : b_a;

    const int tid = threadIdx.x;               // 256
    const int c4  = tid & 15;                  // float4 column 0..15
    const int rg  = tid >> 4;                  // row group 0..15
    const int o   = tid >> 1;                  // epilogue output channel
    const int h   = tid & 1;                   // epilogue K-half

    __shared__ float4 sw[256][9];              // padded W, conflict-free
    __shared__ float4 sm[16][16];              // reduce scratch
    __shared__ float4 segv[D / 4];             // this segment's max vector
    __shared__ int    swork;

    // W -> shared once: coalesced LDG, scattered conflict-free STS.
    {
        const float4* __restrict__ W4g = reinterpret_cast<const float4*>(W);
        #pragma unroll
        for (int i = 0; i < 8; i++) {
            int f = tid + i * 256;             // float4 linear index into W
            float4 v = W4g[f];
            int row = f >> 4;                  // output row 0..127
            int kk  = f & 15;                  // float4 within row
            sw[(row << 1) | (kk >> 3)][kk & 7] = v;
        }
    }
    const float bo = bias[o];

    const float4* __restrict__ xv = reinterpret_cast<const float4*>(x);
    const float NEG = -3.402823466e38f;

    float lmax = 0.0f;                         // relu floor, running block max

    while (true) {
        if (tid == 0) swork = atomicAdd(&g_counter[ctype], 1);
        __syncthreads();                       // also covers sw visibility
        const int g = swork;
        if (g >= NSEG) break;

        const int gs = ptr[g];
        const int ge = ptr[g + 1];

        float4 m0 = make_float4(NEG, NEG, NEG, NEG);
        float4 m1 = m0, m2 = m0, m3 = m0;

        long long row = (long long)gs + rg;
        for (; row + 48 < ge; row += 64) {
            const float4* p = xv + row * (D / 4) + c4;
            float4 v0 = __ldcs(p);
            float4 v1 = __ldcs(p + 16 * (D / 4));
            float4 v2 = __ldcs(p + 32 * (D / 4));
            float4 v3 = __ldcs(p + 48 * (D / 4));
            fmax4(m0, v0); fmax4(m1, v1); fmax4(m2, v2); fmax4(m3, v3);
        }
        // Predicated parallel tail: <=3 independent loads in flight (was a
        // serial MLP=1 loop — the last exposed-latency path in the stream).
        {
            const float4* p = xv + row * (D / 4) + c4;
            const bool p0 = row      < ge;
            const bool p1 = row + 16 < ge;
            const bool p2 = row + 32 < ge;
            float4 v0, v1, v2;
            if (p0) v0 = __ldcs(p);
            if (p1) v1 = __ldcs(p + 16 * (D / 4));
            if (p2) v2 = __ldcs(p + 32 * (D / 4));
            if (p0) fmax4(m0, v0);
            if (p1) fmax4(m1, v1);
            if (p2) fmax4(m2, v2);
        }
        fmax4(m0, m1); fmax4(m2, m3); fmax4(m0, m2);

        sm[rg][c4] = m0;
        __syncthreads();

        if (tid < 16) {
            float4 m = sm[0][tid];
            #pragma unroll
            for (int j = 1; j < 16; j++)
                fmax4(m, sm[j][tid]);
            segv[tid] = m;
        }
        __syncthreads();

        // Epilogue: split-K half-dot from smem W (no register W copy).
        float a0 = 0.f, a1 = 0.f, a2 = 0.f, a3 = 0.f;
        #pragma unroll
        for (int k = 0; k < 8; k++) {
            float4 ww = sw[tid][k];            // W[o, h*32+4k .. +4)
            float4 u  = segv[h * 8 + k];
            a0 = fmaf(ww.x, u.x, a0);
            a1 = fmaf(ww.y, u.y, a1);
            a2 = fmaf(ww.z, u.z, a2);
            a3 = fmaf(ww.w, u.w, a3);
        }
        float hd    = (a0 + a1) + (a2 + a3);
        float other = __shfl_xor_sync(0xffffffffu, hd, 1);
        lmax = fmaxf(lmax, hd + other + bo);
        // next iteration's top-of-loop __syncthreads orders segv reuse
    }

    if (h == 0)
        atomicMax(reinterpret_cast<int*>(out) + o, __float_as_int(lmax));
}

// ---------------------------------------------------------------------------
extern "C" void kernel_launch(void* const* d_in, const int* in_sizes, int n_in,
                              void* d_out, int out_size)
{
    const float* x_a   = (const float*)d_in[0];
    const float* x_b   = (const float*)d_in[1];
    const float* W_a   = (const float*)d_in[2];
    const float* W_b   = (const float*)d_in[3];
    const float* b_a   = (const float*)d_in[4];
    const float* b_b   = (const float*)d_in[5];
    const int*   ptr_a = (const int*)d_in[6];
    const int*   ptr_b = (const int*)d_in[7];
    float* out = (float*)d_out;

    init_kernel<<<1, OUT>>>(out);
    seg_max_linear_kernel<<<NBLK, 256>>>(x_a, x_b, W_a, W_b,
                                         b_a, b_b, ptr_a, ptr_b, out);
}